// round 11
// baseline (speedup 1.0000x reference)
#include <cuda_runtime.h>

// ---------------------------------------------------------------------------
// SparseNeuralNetwork: 256 independent 1->16->8->1 micro-MLPs.
//   out[b,o] = b2[o] + sum_i MLP_{i,o}(x[b,i])
//
// f32x2 packed over SAMPLE PAIRS (weights pre-duplicated in smem), k-outer
// accumulation. R10: NPACK=3 (6 samples/thread) at __launch_bounds__(256,3)
// -> ~85 regs -> 6 warps/SMSP (vs 4 at R9, 8 at R6): the middle of the
// regs-vs-warps curve. Bias folded into the k2=0 FMA. chunk=192, grid=344.
// ---------------------------------------------------------------------------

typedef unsigned long long ull;

// Duplicated compact weights (each scalar stored twice for f32x2 operands).
__device__ float g_w0d[8192];    // [io(256)][k(16)][2]
__device__ float g_b0d[8192];    // [io][k][2]
__device__ float g_w1d[65536];   // [io][k(16)][j(8)][2]
__device__ float g_b1d[4096];    // [io][j(8)][2]
__device__ float g_w2d[4096];    // [io][j(8)][2]

__global__ void gather_kernel(const float* __restrict__ W0,
                              const float* __restrict__ b0,
                              const float* __restrict__ W1,
                              const float* __restrict__ b1,
                              const float* __restrict__ W2,
                              const float* __restrict__ b2,
                              float* __restrict__ out,
                              int out_elems) {
    int t = blockIdx.x * blockDim.x + threadIdx.x;
    if (t < out_elems) out[t] = b2[t & 15];          // preset out = b2[o]
    if (t < 65536) {                                  // w1 dup: [io][k][j][2]
        int j  = (t >> 1) & 7;
        int k  = (t >> 4) & 15;
        int io = t >> 8;
        int r  = io * 8 + j;
        g_w1d[t] = W1[r * 4096 + io * 16 + k];
    }
    if (t < 8192) {                                   // w0/b0 dup: [io][k][2]
        int k  = (t >> 1) & 15;
        int io = t >> 5;
        int r  = io * 16 + k;
        int i  = io >> 4;
        g_w0d[t] = W0[r * 16 + i];
        g_b0d[t] = b0[r];
    }
    if (t < 4096) {                                   // b1/w2 dup: [io][j][2]
        int j  = (t >> 1) & 7;
        int io = t >> 4;
        int r  = io * 8 + j;
        g_b1d[t] = b1[r];
        g_w2d[t] = W2[(io & 15) * 2048 + r];
    }
}

// ---- packed f32x2 helpers --------------------------------------------------
__device__ __forceinline__ void up2(ull v, float& lo, float& hi) {
    asm("mov.b64 {%0, %1}, %2;" : "=f"(lo), "=f"(hi) : "l"(v));
}
__device__ __forceinline__ ull fma2(ull a, ull b, ull c) {
    ull d;
    asm("fma.rn.f32x2 %0, %1, %2, %3;" : "=l"(d) : "l"(a), "l"(b), "l"(c));
    return d;
}
// packed relu: unpack, 2x FMNMX (alu pipe), repack (movs coalesce in SASS)
__device__ __forceinline__ ull relu2(ull v) {
    float a, b;
    up2(v, a, b);
    a = fmaxf(a, 0.0f);
    b = fmaxf(b, 0.0f);
    ull d;
    asm("mov.b64 %0, {%1, %2};" : "=l"(d) : "f"(a), "f"(b));
    return d;
}

// ---------------------------------------------------------------------------
// mlp kernel: blockIdx.x encodes (chunk, i-quarter, o-half):
//   oh = b & 1, iq = (b>>1) & 3, chunk = b >> 3
// block = 256 threads = 8 warps; warp -> output o = oh*8 + warp;
// lane handles 6 samples (3 f32x2 packs), chunk = 192 samples.
// ---------------------------------------------------------------------------
#define NPACK 3   // sample pairs per thread
#define CHUNK 192 // samples per chunk (= 32 lanes * 2 * NPACK)

__global__ __launch_bounds__(256, 3)
void mlp_kernel(const float* __restrict__ x,
                float* __restrict__ out,
                int n) {
    __shared__ float sw1d[8192];   // [ii(4)][oo(8)][k(16)][j(8)][2]
    __shared__ float sw0d[1024];   // [ii][oo][k][2]
    __shared__ float sb0d[1024];
    __shared__ float sb1d[512];    // [ii][oo][j][2]
    __shared__ float sw2d[512];
    __shared__ float sx[4 * CHUNK];

    const int tid  = threadIdx.x;
    const int w    = tid >> 5;
    const int lane = tid & 31;

    const int bidx  = blockIdx.x;
    const int oh    = bidx & 1;
    const int iq    = (bidx >> 1) & 3;
    const int chunk = bidx >> 3;
    const int base  = chunk * CHUNK;

    // ---- stage duplicated weight slices (contiguous per ii) ---------------
    #pragma unroll
    for (int ii = 0; ii < 4; ++ii) {
        const int i   = iq * 4 + ii;
        const int gio = i * 16 + oh * 8;   // first (i,o) of this block's slice
        {
            const float4* s = (const float4*)(g_w1d + gio * 256);
            float4* d = (float4*)(sw1d + ii * 2048);
            for (int t = tid; t < 512; t += 256) d[t] = s[t];
        }
        if (tid < 64) {
            ((float4*)(sw0d + ii * 256))[tid] = ((const float4*)(g_w0d + gio * 32))[tid];
            ((float4*)(sb0d + ii * 256))[tid] = ((const float4*)(g_b0d + gio * 32))[tid];
        }
        if (tid < 32) {
            ((float4*)(sb1d + ii * 128))[tid] = ((const float4*)(g_b1d + gio * 16))[tid];
            ((float4*)(sw2d + ii * 128))[tid] = ((const float4*)(g_w2d + gio * 16))[tid];
        }
    }
    // x transposed: sx[ii][s] = x[(base+s)*16 + (iq*4+ii)]
    for (int e = tid; e < 4 * CHUNK; e += 256) {
        int ii = e / CHUNK, s = e % CHUNK;
        int gs = base + s;
        sx[ii * CHUNK + s] = (gs < n) ? x[gs * 16 + (iq * 4 + ii)] : 0.0f;
    }
    __syncthreads();

    ull outp[NPACK];                 // packed outputs per sample pair
    #pragma unroll
    for (int p = 0; p < NPACK; ++p) outp[p] = 0;

    #pragma unroll 1
    for (int ii = 0; ii < 4; ++ii) {
        const int bio = ii * 8 + w;   // local (ii, oo) slot

        // x packs: 6 consecutive samples -> 3 packs (three LDS.64, 8B align)
        ull xp[NPACK];
        {
            const ull* xs = (const ull*)(sx + ii * CHUNK + 6 * lane);
            xp[0] = xs[0]; xp[1] = xs[1]; xp[2] = xs[2];
        }

        const float* w0base = sw0d + bio * 32;
        const float* b0base = sb0d + bio * 32;
        const float* w1base = sw1d + bio * 256;

        ull acc[NPACK][8];

        #pragma unroll
        for (int k2 = 0; k2 < 8; ++k2) {
            // layer 0 for k = 2*k2 and 2*k2+1 (dup weights, packed samples)
            const ulonglong2 w0p = *(const ulonglong2*)(w0base + k2 * 4);
            const ulonglong2 b0p = *(const ulonglong2*)(b0base + k2 * 4);
            ull ya[NPACK], yb[NPACK];
            #pragma unroll
            for (int p = 0; p < NPACK; ++p) {
                ya[p] = relu2(fma2(w0p.x, xp[p], b0p.x));   // unit k
                yb[p] = relu2(fma2(w0p.y, xp[p], b0p.y));   // unit k+1
            }

            // layer 1 scatter: k row (8 dup weights over j).
            // k2 == 0 initializes accumulators with b1 folded into the FMA.
            if (k2 == 0) {
                const ulonglong2* w1p = (const ulonglong2*)(w1base);
                const ulonglong2* bp  = (const ulonglong2*)(sb1d + bio * 16);
                #pragma unroll
                for (int q = 0; q < 4; ++q) {
                    ulonglong2 v = w1p[q];
                    ulonglong2 b = bp[q];
                    #pragma unroll
                    for (int p = 0; p < NPACK; ++p) {
                        acc[p][2 * q]     = fma2(v.x, ya[p], b.x);
                        acc[p][2 * q + 1] = fma2(v.y, ya[p], b.y);
                    }
                }
            } else {
                const ulonglong2* w1p = (const ulonglong2*)(w1base + (2 * k2) * 16);
                #pragma unroll
                for (int q = 0; q < 4; ++q) {
                    ulonglong2 v = w1p[q];
                    #pragma unroll
                    for (int p = 0; p < NPACK; ++p) {
                        acc[p][2 * q]     = fma2(v.x, ya[p], acc[p][2 * q]);
                        acc[p][2 * q + 1] = fma2(v.y, ya[p], acc[p][2 * q + 1]);
                    }
                }
            }
            // k+1 row
            {
                const ulonglong2* w1p = (const ulonglong2*)(w1base + (2 * k2 + 1) * 16);
                #pragma unroll
                for (int q = 0; q < 4; ++q) {
                    ulonglong2 v = w1p[q];
                    #pragma unroll
                    for (int p = 0; p < NPACK; ++p) {
                        acc[p][2 * q]     = fma2(v.x, yb[p], acc[p][2 * q]);
                        acc[p][2 * q + 1] = fma2(v.y, yb[p], acc[p][2 * q + 1]);
                    }
                }
            }
        }

        // relu + layer-2 fold (still packed over samples)
        {
            const ulonglong2* w2p = (const ulonglong2*)(sw2d + bio * 16);
            #pragma unroll
            for (int q = 0; q < 4; ++q) {
                ulonglong2 v = w2p[q];
                #pragma unroll
                for (int p = 0; p < NPACK; ++p) {
                    outp[p] = fma2(v.x, relu2(acc[p][2 * q]), outp[p]);
                    outp[p] = fma2(v.y, relu2(acc[p][2 * q + 1]), outp[p]);
                }
            }
        }
    }

    // ---- combine i-quarter partials via atomics ----------------------------
    const int o  = oh * 8 + w;
    const int s0 = base + 6 * lane;
    #pragma unroll
    for (int p = 0; p < NPACK; ++p) {
        float v0, v1;
        up2(outp[p], v0, v1);
        int s = s0 + 2 * p;
        if (s + 0 < n) atomicAdd(out + (s + 0) * 16 + o, v0);
        if (s + 1 < n) atomicAdd(out + (s + 1) * 16 + o, v1);
    }
}

extern "C" void kernel_launch(void* const* d_in, const int* in_sizes, int n_in,
                              void* d_out, int out_size) {
    const float *x = nullptr, *W0 = nullptr, *b0 = nullptr, *W1 = nullptr;
    const float *b1 = nullptr, *W2 = nullptr, *b2 = nullptr;
    for (int idx = 0; idx < n_in; ++idx) {
        switch (in_sizes[idx]) {
            case 131072:  x  = (const float*)d_in[idx]; break;   // [8192,16]
            case 65536:   W0 = (const float*)d_in[idx]; break;   // [4096,16]
            case 4096:    b0 = (const float*)d_in[idx]; break;
            case 8388608: W1 = (const float*)d_in[idx]; break;   // [2048,4096]
            case 2048:    b1 = (const float*)d_in[idx]; break;
            case 32768:   W2 = (const float*)d_in[idx]; break;   // [16,2048]
            case 16:      b2 = (const float*)d_in[idx]; break;
            default: break;
        }
    }

    const int n = out_size / 16;

    // gather/dup weights + preset out = b2  (needs >= 131072 threads)
    gather_kernel<<<512, 256>>>(W0, b0, W1, b1, W2, b2, (float*)d_out, out_size);

    const int chunks = (n + CHUNK - 1) / CHUNK;
    mlp_kernel<<<chunks * 8, 256>>>(x, (float*)d_out, n);
}

// round 12
// speedup vs baseline: 1.1056x; 1.1056x over previous
#include <cuda_runtime.h>

// ---------------------------------------------------------------------------
// SparseNeuralNetwork: 256 independent 1->16->8->1 micro-MLPs.
//   out[b,o] = b2[o] + sum_i MLP_{i,o}(x[b,i])
//
// KEY IDEA (R12): each micro-MLP is piecewise-linear in its scalar input x
// with 16 breakpoints (layer-0 relu knees). Precompute, per (i,o) pair and
// per interval m in [0,16], the collapsed coefficients:
//     y1_j(x) = A_j[m]*x + B_j[m]        (8 j's)
// Runtime: idx = #{k : x > s_k} (sorted breakpoints), gather A/B row,
// out += sum_j w2_j * relu(A_j x + B_j).  ~3x fewer flops than direct eval.
// ---------------------------------------------------------------------------

#define SENT 1e30f

// Precomputed tables (global scratch; no allocations).
__device__ float g_tbl[256 * 17 * 20];  // [io][interval][A0,B0,...,A7,B7,pad4]
__device__ float g_thr[256 * 16];       // [io][sorted breakpoints]
__device__ float g_w2c[256 * 8];        // [io][j] output weights

// One thread per (io, j): builds A/B for all 17 intervals of pair io, unit j.
// Also presets out = b2 (grid-stride over out elements).
__global__ void precompute_kernel(const float* __restrict__ W0,
                                  const float* __restrict__ b0,
                                  const float* __restrict__ W1,
                                  const float* __restrict__ b1,
                                  const float* __restrict__ W2,
                                  const float* __restrict__ b2,
                                  float* __restrict__ out,
                                  int out_elems) {
    int t = blockIdx.x * blockDim.x + threadIdx.x;
    if (t < out_elems) out[t] = b2[t & 15];   // preset out = b2[o]

    if (t < 2048) {
        const int io = t >> 3;
        const int j  = t & 7;
        const int i  = io >> 4;
        const int o  = io & 15;

        float w0[16], c0[16], s[16], w1[16];
        #pragma unroll
        for (int k = 0; k < 16; ++k) {
            w0[k] = W0[(io * 16 + k) * 16 + i];
            c0[k] = b0[io * 16 + k];
            w1[k] = W1[(io * 8 + j) * 4096 + io * 16 + k];
            float tk = (w0[k] != 0.0f) ? (-c0[k] / w0[k]) : -SENT;
            if (tk < -SENT) tk = -SENT;
            if (tk >  SENT) tk =  SENT;
            s[k] = tk;
        }
        // fully-unrolled bubble sort (ascending) -> stays in registers
        #pragma unroll
        for (int a = 0; a < 15; ++a) {
            #pragma unroll
            for (int q = 0; q < 15; ++q) {
                if (q < 15 - a) {
                    float lo = fminf(s[q], s[q + 1]);
                    float hi = fmaxf(s[q], s[q + 1]);
                    s[q] = lo; s[q + 1] = hi;
                }
            }
        }
        if (j == 0) {
            #pragma unroll
            for (int k = 0; k < 16; ++k) g_thr[io * 16 + k] = s[k];
        }
        g_w2c[io * 8 + j] = W2[o * 2048 + io * 8 + j];

        const float bj = b1[io * 8 + j];
        #pragma unroll 1
        for (int m = 0; m <= 16; ++m) {
            float lo = (m == 0)  ? -2e30f : s[m - 1];
            float hi = (m == 16) ?  2e30f : s[m];
            float xm = 0.5f * lo + 0.5f * hi;   // representative point
            float A = 0.0f, B = bj;
            #pragma unroll
            for (int k = 0; k < 16; ++k) {
                if (fmaf(w0[k], xm, c0[k]) > 0.0f) {   // unit k active here
                    A += w1[k] * w0[k];
                    B += w1[k] * c0[k];
                }
            }
            g_tbl[(io * 17 + m) * 20 + 2 * j]     = A;
            g_tbl[(io * 17 + m) * 20 + 2 * j + 1] = B;
        }
    }
}

// ---------------------------------------------------------------------------
// Runtime kernel: blockIdx.x encodes (chunk, i-quarter, o-half):
//   oh = b & 1, iq = (b>>1) & 3, chunk = b >> 3
// block = 256 threads = 8 warps; warp -> output o = oh*8 + w;
// lane handles 8 consecutive samples; chunk = 256 samples.
// ---------------------------------------------------------------------------
#define CH 256

// dynamic smem layout (floats):
//   stbl [4][8][17][20] = 10880   piecewise tables for this block's 32 pairs
//   sthr [4][8][16]     =   512   sorted breakpoints
//   sw2  [4][8][8]      =   256   output weights
//   sx   [4][256]       =  1024   x chunk transposed
constexpr int SMEM_FLOATS = 10880 + 512 + 256 + 1024;
constexpr int SMEM_BYTES  = SMEM_FLOATS * 4;   // 50688 B

__global__ __launch_bounds__(256, 3)
void mlp_kernel(const float* __restrict__ x,
                float* __restrict__ out,
                int n) {
    extern __shared__ float sm[];
    float* stbl = sm;             // 10880
    float* sthr = stbl + 10880;   // 512
    float* sw2  = sthr + 512;     // 256
    float* sx   = sw2  + 256;     // 1024

    const int tid  = threadIdx.x;
    const int w    = tid >> 5;
    const int lane = tid & 31;

    const int bidx  = blockIdx.x;
    const int oh    = bidx & 1;
    const int iq    = (bidx >> 1) & 3;
    const int chunk = bidx >> 3;
    const int base  = chunk * CH;

    // ---- stage tables for this block's 32 (i,o) pairs ----------------------
    #pragma unroll
    for (int ii = 0; ii < 4; ++ii) {
        const int gio0 = (iq * 4 + ii) * 16 + oh * 8;   // 8 contiguous pairs
        {
            const float4* s4 = (const float4*)(g_tbl + gio0 * 340);
            float4* d4 = (float4*)(stbl + ii * 2720);
            for (int tt = tid; tt < 680; tt += 256) d4[tt] = s4[tt];
        }
        if (tid < 32)
            ((float4*)(sthr + ii * 128))[tid] =
                ((const float4*)(g_thr + gio0 * 16))[tid];
        if (tid < 16)
            ((float4*)(sw2 + ii * 64))[tid] =
                ((const float4*)(g_w2c + gio0 * 8))[tid];
    }
    // x transposed: sx[ii][s] = x[(base+s)*16 + (iq*4+ii)]
    for (int e = tid; e < 4 * CH; e += 256) {
        int ii = e >> 8, s = e & 255;
        int gs = base + s;
        sx[ii * CH + s] = (gs < n) ? x[gs * 16 + iq * 4 + ii] : 0.0f;
    }
    __syncthreads();

    float acc[8];
    #pragma unroll
    for (int p = 0; p < 8; ++p) acc[p] = 0.0f;

    #pragma unroll 1
    for (int ii = 0; ii < 4; ++ii) {
        const int bio = ii * 8 + w;

        // breakpoints + w2 into registers (warp-uniform broadcast LDS)
        float s[16];
        {
            const float4* sp = (const float4*)(sthr + bio * 16);
            #pragma unroll
            for (int q = 0; q < 4; ++q) {
                float4 v = sp[q];
                s[4 * q] = v.x; s[4 * q + 1] = v.y;
                s[4 * q + 2] = v.z; s[4 * q + 3] = v.w;
            }
        }
        float w2r[8];
        {
            const float4* wp = (const float4*)(sw2 + bio * 8);
            float4 a = wp[0], b = wp[1];
            w2r[0] = a.x; w2r[1] = a.y; w2r[2] = a.z; w2r[3] = a.w;
            w2r[4] = b.x; w2r[5] = b.y; w2r[6] = b.z; w2r[7] = b.w;
        }
        // 8 samples for this lane
        float xs[8];
        {
            const float4* xp = (const float4*)(sx + ii * CH + 8 * lane);
            float4 a = xp[0], b = xp[1];
            xs[0] = a.x; xs[1] = a.y; xs[2] = a.z; xs[3] = a.w;
            xs[4] = b.x; xs[5] = b.y; xs[6] = b.z; xs[7] = b.w;
        }

        const float* tb = stbl + ii * 2720 + w * 340;

        #pragma unroll
        for (int p = 0; p < 8; ++p) {
            const float xv = xs[p];
            // interval index: tree-summed 16 compares
            int c0 = (xv > s[0])  + (xv > s[1])  + (xv > s[2])  + (xv > s[3]);
            int c1 = (xv > s[4])  + (xv > s[5])  + (xv > s[6])  + (xv > s[7]);
            int c2 = (xv > s[8])  + (xv > s[9])  + (xv > s[10]) + (xv > s[11]);
            int c3 = (xv > s[12]) + (xv > s[13]) + (xv > s[14]) + (xv > s[15]);
            const int idx = (c0 + c1) + (c2 + c3);

            const float4* row = (const float4*)(tb + idx * 20);
            float4 r0 = row[0], r1 = row[1], r2 = row[2], r3 = row[3];
            float a = acc[p];
            a = fmaf(w2r[0], fmaxf(fmaf(r0.x, xv, r0.y), 0.0f), a);
            a = fmaf(w2r[1], fmaxf(fmaf(r0.z, xv, r0.w), 0.0f), a);
            a = fmaf(w2r[2], fmaxf(fmaf(r1.x, xv, r1.y), 0.0f), a);
            a = fmaf(w2r[3], fmaxf(fmaf(r1.z, xv, r1.w), 0.0f), a);
            a = fmaf(w2r[4], fmaxf(fmaf(r2.x, xv, r2.y), 0.0f), a);
            a = fmaf(w2r[5], fmaxf(fmaf(r2.z, xv, r2.w), 0.0f), a);
            a = fmaf(w2r[6], fmaxf(fmaf(r3.x, xv, r3.y), 0.0f), a);
            a = fmaf(w2r[7], fmaxf(fmaf(r3.z, xv, r3.w), 0.0f), a);
            acc[p] = a;
        }
    }

    // ---- combine i-quarter partials via atomics ----------------------------
    const int o  = oh * 8 + w;
    const int s0 = base + 8 * lane;
    #pragma unroll
    for (int p = 0; p < 8; ++p)
        if (s0 + p < n) atomicAdd(out + (s0 + p) * 16 + o, acc[p]);
}

extern "C" void kernel_launch(void* const* d_in, const int* in_sizes, int n_in,
                              void* d_out, int out_size) {
    const float *x = nullptr, *W0 = nullptr, *b0 = nullptr, *W1 = nullptr;
    const float *b1 = nullptr, *W2 = nullptr, *b2 = nullptr;
    for (int idx = 0; idx < n_in; ++idx) {
        switch (in_sizes[idx]) {
            case 131072:  x  = (const float*)d_in[idx]; break;   // [8192,16]
            case 65536:   W0 = (const float*)d_in[idx]; break;   // [4096,16]
            case 4096:    b0 = (const float*)d_in[idx]; break;
            case 8388608: W1 = (const float*)d_in[idx]; break;   // [2048,4096]
            case 2048:    b1 = (const float*)d_in[idx]; break;
            case 32768:   W2 = (const float*)d_in[idx]; break;   // [16,2048]
            case 16:      b2 = (const float*)d_in[idx]; break;
            default: break;
        }
    }

    const int n = out_size / 16;

    // build piecewise-linear tables + preset out = b2
    precompute_kernel<<<512, 256>>>(W0, b0, W1, b1, W2, b2,
                                    (float*)d_out, out_size);

    cudaFuncSetAttribute(mlp_kernel,
                         cudaFuncAttributeMaxDynamicSharedMemorySize, SMEM_BYTES);
    const int chunks = (n + CH - 1) / CH;
    mlp_kernel<<<chunks * 8, 256, SMEM_BYTES>>>(x, (float*)d_out, n);
}

// round 14
// speedup vs baseline: 1.2113x; 1.0956x over previous
#include <cuda_runtime.h>

// ---------------------------------------------------------------------------
// SparseNeuralNetwork: 256 independent 1->16->8->1 micro-MLPs.
//   out[b,o] = b2[o] + sum_i MLP_{i,o}(x[b,i])
//
// Each micro-MLP is piecewise-linear in its scalar input x with 16
// breakpoints (layer-0 relu knees). Precompute per (i,o) and interval m:
//     y1_j(x) = A_j[m]*x + B_j[m]        (8 j's)
// Runtime: idx = #{k : x > s_k}, gather A/B row, out += sum_j w2_j*relu(.).
//
// R13: precompute rebuilt -- items spread across all 512 blocks (one per
// 64-thread group) and incremental toggle updates (A += da, B -= da*s)
// replace the 17x16 active-set re-evaluation. mlp_kernel unchanged from R12.
// ---------------------------------------------------------------------------

#define SENT 1e30f

// Precomputed tables (global scratch; no allocations).
__device__ float g_tbl[256 * 17 * 20];  // [io][interval][A0,B0,...,A7,B7,pad4]
__device__ float g_thr[256 * 16];       // [io][sorted breakpoints]
__device__ float g_w2c[256 * 8];        // [io][j] output weights

// Work item (io, j) = blockIdx.x*4 + (tid>>6), executed by one thread per
// 64-thread group -> 2048 items spread across all 512 blocks / all SMs.
// Also presets out = b2 (t-strided).
__global__ void precompute_kernel(const float* __restrict__ W0,
                                  const float* __restrict__ b0,
                                  const float* __restrict__ W1,
                                  const float* __restrict__ b1,
                                  const float* __restrict__ W2,
                                  const float* __restrict__ b2,
                                  float* __restrict__ out,
                                  int out_elems) {
    int t = blockIdx.x * blockDim.x + threadIdx.x;
    if (t < out_elems) out[t] = b2[t & 15];   // preset out = b2[o]

    if ((threadIdx.x & 63) == 0) {
        const int item = blockIdx.x * 4 + (threadIdx.x >> 6);
        if (item < 2048) {
            const int io = item >> 3;
            const int j  = item & 7;
            const int i  = io >> 4;
            const int o  = io & 15;

            float s[16], da[16];
            float A = 0.0f;                      // slope at x -> -inf
            float B = b1[io * 8 + j];            // intercept at x -> -inf

            #pragma unroll
            for (int k = 0; k < 16; ++k) {
                const float w0k = W0[(io * 16 + k) * 16 + i];
                const float c0k = b0[io * 16 + k];
                const float w1k = W1[(io * 8 + j) * 4096 + io * 16 + k];
                float sk;
                float dak;
                if (w0k != 0.0f) {
                    sk = -c0k / w0k;
                    sk = fminf(fmaxf(sk, -SENT), SENT);
                    dak = w1k * fabsf(w0k);      // upward-crossing delta slope
                    if (w0k < 0.0f) {            // active at -inf
                        A += w1k * w0k;
                        B += w1k * c0k;
                    }
                } else {
                    sk  = -SENT;                 // sentinel: toggle is a no-op
                    dak = 0.0f;
                    if (c0k > 0.0f) B += w1k * c0k;   // always-active unit
                }
                s[k]  = sk;
                da[k] = dak;
            }

            // unrolled bubble sort ascending by s, carrying da
            #pragma unroll
            for (int a = 0; a < 15; ++a) {
                #pragma unroll
                for (int q = 0; q < 15; ++q) {
                    if (q < 15 - a) {
                        if (s[q] > s[q + 1]) {
                            float ts = s[q];  s[q]  = s[q + 1];  s[q + 1]  = ts;
                            float td = da[q]; da[q] = da[q + 1]; da[q + 1] = td;
                        }
                    }
                }
            }

            if (j == 0) {
                #pragma unroll
                for (int k = 0; k < 16; ++k) g_thr[io * 16 + k] = s[k];
            }
            g_w2c[io * 8 + j] = W2[o * 2048 + io * 8 + j];

            // emit rows: interval m has A,B after m upward toggles.
            // db = -da * s  (exact for both signs of w0; 0 for sentinels)
            g_tbl[(io * 17 + 0) * 20 + 2 * j]     = A;
            g_tbl[(io * 17 + 0) * 20 + 2 * j + 1] = B;
            #pragma unroll
            for (int m = 1; m <= 16; ++m) {
                A += da[m - 1];
                B = fmaf(-da[m - 1], s[m - 1], B);
                g_tbl[(io * 17 + m) * 20 + 2 * j]     = A;
                g_tbl[(io * 17 + m) * 20 + 2 * j + 1] = B;
            }
        }
    }
}

// ---------------------------------------------------------------------------
// Runtime kernel (unchanged from R12): blockIdx.x encodes (chunk, iq, oh):
//   oh = b & 1, iq = (b>>1) & 3, chunk = b >> 3
// block = 256 threads = 8 warps; warp -> output o = oh*8 + w;
// lane handles 8 consecutive samples; chunk = 256 samples.
// ---------------------------------------------------------------------------
#define CH 256

constexpr int SMEM_FLOATS = 10880 + 512 + 256 + 1024;
constexpr int SMEM_BYTES  = SMEM_FLOATS * 4;   // 50688 B

__global__ __launch_bounds__(256, 3)
void mlp_kernel(const float* __restrict__ x,
                float* __restrict__ out,
                int n) {
    extern __shared__ float sm[];
    float* stbl = sm;             // 10880
    float* sthr = stbl + 10880;   // 512
    float* sw2  = sthr + 512;     // 256
    float* sx   = sw2  + 256;     // 1024

    const int tid  = threadIdx.x;
    const int w    = tid >> 5;
    const int lane = tid & 31;

    const int bidx  = blockIdx.x;
    const int oh    = bidx & 1;
    const int iq    = (bidx >> 1) & 3;
    const int chunk = bidx >> 3;
    const int base  = chunk * CH;

    // ---- stage tables for this block's 32 (i,o) pairs ----------------------
    #pragma unroll
    for (int ii = 0; ii < 4; ++ii) {
        const int gio0 = (iq * 4 + ii) * 16 + oh * 8;   // 8 contiguous pairs
        {
            const float4* s4 = (const float4*)(g_tbl + gio0 * 340);
            float4* d4 = (float4*)(stbl + ii * 2720);
            for (int tt = tid; tt < 680; tt += 256) d4[tt] = s4[tt];
        }
        if (tid < 32)
            ((float4*)(sthr + ii * 128))[tid] =
                ((const float4*)(g_thr + gio0 * 16))[tid];
        if (tid < 16)
            ((float4*)(sw2 + ii * 64))[tid] =
                ((const float4*)(g_w2c + gio0 * 8))[tid];
    }
    // x transposed: sx[ii][s] = x[(base+s)*16 + (iq*4+ii)]
    for (int e = tid; e < 4 * CH; e += 256) {
        int ii = e >> 8, s = e & 255;
        int gs = base + s;
        sx[ii * CH + s] = (gs < n) ? x[gs * 16 + iq * 4 + ii] : 0.0f;
    }
    __syncthreads();

    float acc[8];
    #pragma unroll
    for (int p = 0; p < 8; ++p) acc[p] = 0.0f;

    #pragma unroll 1
    for (int ii = 0; ii < 4; ++ii) {
        const int bio = ii * 8 + w;

        // breakpoints + w2 into registers (warp-uniform broadcast LDS)
        float s[16];
        {
            const float4* sp = (const float4*)(sthr + bio * 16);
            #pragma unroll
            for (int q = 0; q < 4; ++q) {
                float4 v = sp[q];
                s[4 * q] = v.x; s[4 * q + 1] = v.y;
                s[4 * q + 2] = v.z; s[4 * q + 3] = v.w;
            }
        }
        float w2r[8];
        {
            const float4* wp = (const float4*)(sw2 + bio * 8);
            float4 a = wp[0], b = wp[1];
            w2r[0] = a.x; w2r[1] = a.y; w2r[2] = a.z; w2r[3] = a.w;
            w2r[4] = b.x; w2r[5] = b.y; w2r[6] = b.z; w2r[7] = b.w;
        }
        // 8 samples for this lane
        float xs[8];
        {
            const float4* xp = (const float4*)(sx + ii * CH + 8 * lane);
            float4 a = xp[0], b = xp[1];
            xs[0] = a.x; xs[1] = a.y; xs[2] = a.z; xs[3] = a.w;
            xs[4] = b.x; xs[5] = b.y; xs[6] = b.z; xs[7] = b.w;
        }

        const float* tb = stbl + ii * 2720 + w * 340;

        #pragma unroll
        for (int p = 0; p < 8; ++p) {
            const float xv = xs[p];
            // interval index: tree-summed 16 compares
            int c0 = (xv > s[0])  + (xv > s[1])  + (xv > s[2])  + (xv > s[3]);
            int c1 = (xv > s[4])  + (xv > s[5])  + (xv > s[6])  + (xv > s[7]);
            int c2 = (xv > s[8])  + (xv > s[9])  + (xv > s[10]) + (xv > s[11]);
            int c3 = (xv > s[12]) + (xv > s[13]) + (xv > s[14]) + (xv > s[15]);
            const int idx = (c0 + c1) + (c2 + c3);

            const float4* row = (const float4*)(tb + idx * 20);
            float4 r0 = row[0], r1 = row[1], r2 = row[2], r3 = row[3];
            float a = acc[p];
            a = fmaf(w2r[0], fmaxf(fmaf(r0.x, xv, r0.y), 0.0f), a);
            a = fmaf(w2r[1], fmaxf(fmaf(r0.z, xv, r0.w), 0.0f), a);
            a = fmaf(w2r[2], fmaxf(fmaf(r1.x, xv, r1.y), 0.0f), a);
            a = fmaf(w2r[3], fmaxf(fmaf(r1.z, xv, r1.w), 0.0f), a);
            a = fmaf(w2r[4], fmaxf(fmaf(r2.x, xv, r2.y), 0.0f), a);
            a = fmaf(w2r[5], fmaxf(fmaf(r2.z, xv, r2.w), 0.0f), a);
            a = fmaf(w2r[6], fmaxf(fmaf(r3.x, xv, r3.y), 0.0f), a);
            a = fmaf(w2r[7], fmaxf(fmaf(r3.z, xv, r3.w), 0.0f), a);
            acc[p] = a;
        }
    }

    // ---- combine i-quarter partials via atomics ----------------------------
    const int o  = oh * 8 + w;
    const int s0 = base + 8 * lane;
    #pragma unroll
    for (int p = 0; p < 8; ++p)
        if (s0 + p < n) atomicAdd(out + (s0 + p) * 16 + o, acc[p]);
}

extern "C" void kernel_launch(void* const* d_in, const int* in_sizes, int n_in,
                              void* d_out, int out_size) {
    const float *x = nullptr, *W0 = nullptr, *b0 = nullptr, *W1 = nullptr;
    const float *b1 = nullptr, *W2 = nullptr, *b2 = nullptr;
    for (int idx = 0; idx < n_in; ++idx) {
        switch (in_sizes[idx]) {
            case 131072:  x  = (const float*)d_in[idx]; break;   // [8192,16]
            case 65536:   W0 = (const float*)d_in[idx]; break;   // [4096,16]
            case 4096:    b0 = (const float*)d_in[idx]; break;
            case 8388608: W1 = (const float*)d_in[idx]; break;   // [2048,4096]
            case 2048:    b1 = (const float*)d_in[idx]; break;
            case 32768:   W2 = (const float*)d_in[idx]; break;   // [16,2048]
            case 16:      b2 = (const float*)d_in[idx]; break;
            default: break;
        }
    }

    const int n = out_size / 16;

    // build piecewise-linear tables + preset out = b2
    precompute_kernel<<<512, 256>>>(W0, b0, W1, b1, W2, b2,
                                    (float*)d_out, out_size);

    cudaFuncSetAttribute(mlp_kernel,
                         cudaFuncAttributeMaxDynamicSharedMemorySize, SMEM_BYTES);
    const int chunks = (n + CH - 1) / CH;
    mlp_kernel<<<chunks * 8, 256, SMEM_BYTES>>>(x, (float*)d_out, n);
}

// round 17
// speedup vs baseline: 1.4250x; 1.1764x over previous
#include <cuda_runtime.h>

// ---------------------------------------------------------------------------
// SparseNeuralNetwork: 256 independent 1->16->8->1 micro-MLPs, piecewise-
// linear collapse:  y1_j(x) = A_j[m] x + B_j[m]  on interval m of 17.
// R15: warp-parallel precompute (shfl sort + scan, one warp per (io,j)),
// runtime split 2 i's/block (grid=512, 4 blocks/SM, single wave), and
// FSET-mask interval indexing.
// ---------------------------------------------------------------------------

#define SENT 1e30f

__device__ float g_tbl[256 * 17 * 20];  // [io][interval][A0,B0,...,A7,B7,pad4]
__device__ float g_thr[256 * 16];       // [io][sorted breakpoints]
__device__ float g_w2c[256 * 8];        // [io][j]

// One warp per item (io, j): lanes 0-15 carry the 16 layer-0 units.
// Sort breakpoints via odd-even transposition (shfl), build A/B via prefix
// scan of (da, da*s). Also presets out = b2.
__global__ void precompute_kernel(const float* __restrict__ W0,
                                  const float* __restrict__ b0,
                                  const float* __restrict__ W1,
                                  const float* __restrict__ b1,
                                  const float* __restrict__ W2,
                                  const float* __restrict__ b2,
                                  float* __restrict__ out,
                                  int out_elems) {
    const int tid = threadIdx.x;
    const int t   = blockIdx.x * 256 + tid;
    for (int e = t; e < out_elems; e += 65536) out[e] = b2[e & 15];

    const int gw   = t >> 5;       // warp id = item id (0..2047)
    const int lane = tid & 31;
    if (gw >= 2048) return;
    const int io = gw >> 3;
    const int j  = gw & 7;
    const int i  = io >> 4;
    const int o  = io & 15;
    const int k  = lane & 15;

    float s, da, a0c = 0.0f, b0c = 0.0f;
    {
        const float w0k = W0[(io * 16 + k) * 16 + i];
        const float c0k = b0[io * 16 + k];
        const float w1k = W1[(io * 8 + j) * 4096 + io * 16 + k];
        if (w0k != 0.0f) {
            s  = fminf(fmaxf(-c0k / w0k, -SENT), SENT);
            da = w1k * fabsf(w0k);
            if (w0k < 0.0f) { a0c = w1k * w0k; b0c = w1k * c0k; }
        } else {
            s  = -SENT;
            da = 0.0f;
            if (c0k > 0.0f) b0c = w1k * c0k;
        }
    }
    if (lane >= 16) { a0c = 0.0f; b0c = 0.0f; }

    // A0/B0: reduce lanes 0-15 (xor 1,2,4,8 stays within the 16-group)
    float A0 = a0c, B0 = b0c;
    #pragma unroll
    for (int d = 1; d < 16; d <<= 1) {
        A0 += __shfl_xor_sync(0xffffffffu, A0, d);
        B0 += __shfl_xor_sync(0xffffffffu, B0, d);
    }
    B0 += b1[io * 8 + j];

    // odd-even transposition sort of (s, da) over lanes 0-15, 16 phases
    #pragma unroll
    for (int ph = 0; ph < 16; ++ph) {
        int partner;
        if ((ph & 1) == 0) {
            partner = lane ^ 1;
        } else {
            int l = lane & 15;
            partner = (l == 0 || l == 15) ? lane
                                          : ((l & 1) ? lane + 1 : lane - 1);
        }
        float s2  = __shfl_sync(0xffffffffu, s,  partner);
        float da2 = __shfl_sync(0xffffffffu, da, partner);
        if (partner != lane) {
            bool take = (partner > lane) ? (s2 < s) : (s2 > s);
            if (take) { s = s2; da = da2; }
        }
    }

    // inclusive scans of da and da*s over lanes 0-15
    float pda = da, pds = da * s;
    #pragma unroll
    for (int d = 1; d < 16; d <<= 1) {
        float u = __shfl_up_sync(0xffffffffu, pda, d);
        float v = __shfl_up_sync(0xffffffffu, pds, d);
        if ((lane & 15) >= d) { pda += u; pds += v; }
    }

    if (lane < 16) {
        if (j == 0) g_thr[io * 16 + lane] = s;
        // interval m = lane+1: A = A0 + prefix(da), B = B0 - prefix(da*s)
        const int m = lane + 1;
        g_tbl[(io * 17 + m) * 20 + 2 * j]     = A0 + pda;
        g_tbl[(io * 17 + m) * 20 + 2 * j + 1] = B0 - pds;
        if (lane == 0) {
            g_tbl[(io * 17) * 20 + 2 * j]     = A0;
            g_tbl[(io * 17) * 20 + 2 * j + 1] = B0;
            g_w2c[io * 8 + j] = W2[o * 2048 + io * 8 + j];
        }
    }
}

// ---------------------------------------------------------------------------
// Runtime kernel: blockIdx.x encodes (chunk, i-eighth, o-half):
//   oh = b & 1, ih = (b>>1) & 7, chunk = b >> 4
// block = 256 threads = 8 warps; warp -> output o = oh*8 + w;
// lane handles 8 consecutive samples; chunk = 256 samples; 2 i's per block.
// ---------------------------------------------------------------------------
#define CH 256

// dyn smem (floats): stbl 2*8*340=5440, sthr 2*128=256, sw2 2*64=128, sx 512
constexpr int SMEM_FLOATS = 5440 + 256 + 128 + 512;
constexpr int SMEM_BYTES  = SMEM_FLOATS * 4;   // 25344 B

__device__ __forceinline__ unsigned maskgt(float a, float b) {
    unsigned r;
    asm("set.gt.u32.f32 %0, %1, %2;" : "=r"(r) : "f"(a), "f"(b));
    return r;   // 0xFFFFFFFF if a > b else 0
}

__global__ __launch_bounds__(256, 4)
void mlp_kernel(const float* __restrict__ x,
                float* __restrict__ out,
                int n) {
    extern __shared__ float sm[];
    float* stbl = sm;            // 5440
    float* sthr = stbl + 5440;   // 256
    float* sw2  = sthr + 256;    // 128
    float* sx   = sw2  + 128;    // 512

    const int tid  = threadIdx.x;
    const int w    = tid >> 5;
    const int lane = tid & 31;

    const int bidx  = blockIdx.x;
    const int oh    = bidx & 1;
    const int ih    = (bidx >> 1) & 7;
    const int chunk = bidx >> 4;
    const int base  = chunk * CH;

    // ---- stage tables for this block's 16 (i,o) pairs ----------------------
    #pragma unroll
    for (int ii = 0; ii < 2; ++ii) {
        const int gio0 = (ih * 2 + ii) * 16 + oh * 8;   // 8 contiguous pairs
        {
            const float4* s4 = (const float4*)(g_tbl + gio0 * 340);
            float4* d4 = (float4*)(stbl + ii * 2720);
            for (int tt = tid; tt < 680; tt += 256) d4[tt] = s4[tt];
        }
        if (tid < 32)
            ((float4*)(sthr + ii * 128))[tid] =
                ((const float4*)(g_thr + gio0 * 16))[tid];
        if (tid < 16)
            ((float4*)(sw2 + ii * 64))[tid] =
                ((const float4*)(g_w2c + gio0 * 8))[tid];
    }
    // x transposed: sx[ii][s] = x[(base+s)*16 + (ih*2+ii)]
    for (int e = tid; e < 2 * CH; e += 256) {
        int ii = e >> 8, s = e & 255;
        int gs = base + s;
        sx[ii * CH + s] = (gs < n) ? x[gs * 16 + ih * 2 + ii] : 0.0f;
    }
    __syncthreads();

    float acc[8];
    #pragma unroll
    for (int p = 0; p < 8; ++p) acc[p] = 0.0f;

    #pragma unroll 1
    for (int ii = 0; ii < 2; ++ii) {
        const int bio = ii * 8 + w;

        // breakpoints + w2 into registers (warp-uniform broadcast LDS)
        float s[16];
        {
            const float4* sp = (const float4*)(sthr + bio * 16);
            #pragma unroll
            for (int q = 0; q < 4; ++q) {
                float4 v = sp[q];
                s[4 * q] = v.x; s[4 * q + 1] = v.y;
                s[4 * q + 2] = v.z; s[4 * q + 3] = v.w;
            }
        }
        float w2r[8];
        {
            const float4* wp = (const float4*)(sw2 + bio * 8);
            float4 a = wp[0], b = wp[1];
            w2r[0] = a.x; w2r[1] = a.y; w2r[2] = a.z; w2r[3] = a.w;
            w2r[4] = b.x; w2r[5] = b.y; w2r[6] = b.z; w2r[7] = b.w;
        }
        // 8 samples for this lane
        float xs[8];
        {
            const float4* xp = (const float4*)(sx + ii * CH + 8 * lane);
            float4 a = xp[0], b = xp[1];
            xs[0] = a.x; xs[1] = a.y; xs[2] = a.z; xs[3] = a.w;
            xs[4] = b.x; xs[5] = b.y; xs[6] = b.z; xs[7] = b.w;
        }

        const float* tb = stbl + ii * 2720 + w * 340;

        #pragma unroll
        for (int p = 0; p < 8; ++p) {
            const float xv = xs[p];
            // interval index via FSET masks (each mask = 0 or -1)
            unsigned m0 = maskgt(xv, s[0])  + maskgt(xv, s[1])
                        + maskgt(xv, s[2])  + maskgt(xv, s[3]);
            unsigned m1 = maskgt(xv, s[4])  + maskgt(xv, s[5])
                        + maskgt(xv, s[6])  + maskgt(xv, s[7]);
            unsigned m2 = maskgt(xv, s[8])  + maskgt(xv, s[9])
                        + maskgt(xv, s[10]) + maskgt(xv, s[11]);
            unsigned m3 = maskgt(xv, s[12]) + maskgt(xv, s[13])
                        + maskgt(xv, s[14]) + maskgt(xv, s[15]);
            const int idx = -(int)(m0 + m1 + m2 + m3);

            const float4* row = (const float4*)(tb + idx * 20);
            float4 r0 = row[0], r1 = row[1], r2 = row[2], r3 = row[3];
            float a = acc[p];
            a = fmaf(w2r[0], fmaxf(fmaf(r0.x, xv, r0.y), 0.0f), a);
            a = fmaf(w2r[1], fmaxf(fmaf(r0.z, xv, r0.w), 0.0f), a);
            a = fmaf(w2r[2], fmaxf(fmaf(r1.x, xv, r1.y), 0.0f), a);
            a = fmaf(w2r[3], fmaxf(fmaf(r1.z, xv, r1.w), 0.0f), a);
            a = fmaf(w2r[4], fmaxf(fmaf(r2.x, xv, r2.y), 0.0f), a);
            a = fmaf(w2r[5], fmaxf(fmaf(r2.z, xv, r2.w), 0.0f), a);
            a = fmaf(w2r[6], fmaxf(fmaf(r3.x, xv, r3.y), 0.0f), a);
            a = fmaf(w2r[7], fmaxf(fmaf(r3.z, xv, r3.w), 0.0f), a);
            acc[p] = a;
        }
    }

    // ---- combine i-group partials via atomics ------------------------------
    const int o  = oh * 8 + w;
    const int s0 = base + 8 * lane;
    #pragma unroll
    for (int p = 0; p < 8; ++p)
        if (s0 + p < n) atomicAdd(out + (s0 + p) * 16 + o, acc[p]);
}

extern "C" void kernel_launch(void* const* d_in, const int* in_sizes, int n_in,
                              void* d_out, int out_size) {
    const float *x = nullptr, *W0 = nullptr, *b0 = nullptr, *W1 = nullptr;
    const float *b1 = nullptr, *W2 = nullptr, *b2 = nullptr;
    for (int idx = 0; idx < n_in; ++idx) {
        switch (in_sizes[idx]) {
            case 131072:  x  = (const float*)d_in[idx]; break;   // [8192,16]
            case 65536:   W0 = (const float*)d_in[idx]; break;   // [4096,16]
            case 4096:    b0 = (const float*)d_in[idx]; break;
            case 8388608: W1 = (const float*)d_in[idx]; break;   // [2048,4096]
            case 2048:    b1 = (const float*)d_in[idx]; break;
            case 32768:   W2 = (const float*)d_in[idx]; break;   // [16,2048]
            case 16:      b2 = (const float*)d_in[idx]; break;
            default: break;
        }
    }

    const int n = out_size / 16;

    // warp-parallel table build + preset out = b2
    precompute_kernel<<<256, 256>>>(W0, b0, W1, b1, W2, b2,
                                    (float*)d_out, out_size);

    cudaFuncSetAttribute(mlp_kernel,
                         cudaFuncAttributeMaxDynamicSharedMemorySize, SMEM_BYTES);
    const int chunks = (n + CH - 1) / CH;
    mlp_kernel<<<chunks * 16, 256, SMEM_BYTES>>>(x, (float*)d_out, n);
}